// round 13
// baseline (speedup 1.0000x reference)
#include <cuda_runtime.h>
#include <cstdint>

#define NUM_BINS 20
#define CWARPS 16          // consumer warps
#define CTHREADS 512       // consumer threads
#define THREADS 544        // + 1 producer warp
#define GRID 148           // persistent: 1 CTA/SM, single wave
#define STAGES 4
#define TILE_F4 1024       // float4 per array per tile (16KB)
#define TILE_BYTES 16384
#define STAGE_BYTES (2 * TILE_BYTES)
#define PACK 512.0f        // packed cell: 512*count + sum_sq_err
                           // <=224 elem/thread -> sum-part < 256 = PACK/2: exact

#define SMEM_HIST_FLOATS (CWARPS * NUM_BINS * 32)               // 10240 = 40KB
#define SMEM_TILES_OFF   (SMEM_HIST_FLOATS * 4)                 // 40960
#define SMEM_FULL_OFF    (SMEM_TILES_OFF + STAGES * STAGE_BYTES)
#define SMEM_EMPTY_OFF   (SMEM_FULL_OFF + STAGES * 8)
#define SMEM_SIZE        (SMEM_EMPTY_OFF + STAGES * 8)

__device__ float2 g_part[NUM_BINS * GRID];
__device__ unsigned g_done;   // zero at module load; reset by last block

// ── PTX helpers ─────────────────────────────────────────────────────────
__device__ __forceinline__ uint32_t smem_u32(const void* p) {
    uint32_t a;
    asm("{ .reg .u64 t; cvta.to.shared.u64 t, %1; cvt.u32.u64 %0, t; }"
        : "=r"(a) : "l"(p));
    return a;
}
__device__ __forceinline__ void mbar_init(uint32_t bar, uint32_t cnt) {
    asm volatile("mbarrier.init.shared.b64 [%0], %1;" :: "r"(bar), "r"(cnt) : "memory");
}
__device__ __forceinline__ void mbar_expect_tx(uint32_t bar, uint32_t bytes) {
    asm volatile("mbarrier.arrive.expect_tx.shared.b64 _, [%0], %1;"
                 :: "r"(bar), "r"(bytes) : "memory");
}
__device__ __forceinline__ void mbar_arrive(uint32_t bar) {
    asm volatile("mbarrier.arrive.shared.b64 _, [%0];" :: "r"(bar) : "memory");
}
__device__ __forceinline__ void mbar_wait(uint32_t bar, uint32_t parity) {
    asm volatile(
        "{\n\t.reg .pred P;\n\t"
        "W%=:\n\t"
        "mbarrier.try_wait.parity.acquire.cta.shared::cta.b64 P, [%0], %1, 0x989680;\n\t"
        "@P bra D%=;\n\t"
        "bra W%=;\n\t"
        "D%=:\n\t}"
        :: "r"(bar), "r"(parity) : "memory");
}
__device__ __forceinline__ void bulk_g2s(uint32_t dst, const void* src,
                                         uint32_t bytes, uint32_t bar) {
    asm volatile(
        "cp.async.bulk.shared::cta.global.mbarrier::complete_tx::bytes "
        "[%0], [%1], %2, [%3];"
        :: "r"(dst), "l"(src), "r"(bytes), "r"(bar) : "memory");
}

// ── packed histogram update for 4 element-pairs ─────────────────────────
__device__ __forceinline__ void process4(float* my, float4 p, float4 t) {
    float d0 = p.x - t.x, d1 = p.y - t.y, d2 = p.z - t.z, d3 = p.w - t.w;
    float v0 = fmaf(d0, d0, PACK), v1 = fmaf(d1, d1, PACK);
    float v2 = fmaf(d2, d2, PACK), v3 = fmaf(d3, d3, PACK);
    // target in [0,1): trunc == floor, only upper clamp needed
    int b0 = min((int)(t.x * 20.0f), NUM_BINS - 1);
    int b1 = min((int)(t.y * 20.0f), NUM_BINS - 1);
    int b2 = min((int)(t.z * 20.0f), NUM_BINS - 1);
    int b3 = min((int)(t.w * 20.0f), NUM_BINS - 1);
    my[b0 * 32] += v0;
    my[b1 * 32] += v1;
    my[b2 * 32] += v2;
    my[b3 * 32] += v3;
}

__global__ __launch_bounds__(THREADS, 1) void dwmse_hybrid_kernel(
    const float4* __restrict__ pred,
    const float4* __restrict__ target,
    int n4, float* __restrict__ out, int n)
{
    extern __shared__ char smem[];
    float* hist = (float*)smem;
    const uint32_t sbase = smem_u32(smem);

    __shared__ float2 s_red[NUM_BINS * CWARPS];
    __shared__ bool s_is_last;
    __shared__ float f_sum[NUM_BINS], f_cnt[NUM_BINS], f_w[NUM_BINS];

    const int tid = threadIdx.x;
    const int lane = tid & 31;
    const int warp = tid >> 5;
    const int bid = blockIdx.x;
    float* my = hist + warp * (NUM_BINS * 32) + lane;   // valid for warp < 16

    for (int i = tid; i < SMEM_HIST_FLOATS; i += THREADS) hist[i] = 0.0f;

    if (tid == 0) {
        for (int s = 0; s < STAGES; s++) {
            mbar_init(sbase + SMEM_FULL_OFF + s * 8, 1);        // tx-based
            mbar_init(sbase + SMEM_EMPTY_OFF + s * 8, CWARPS);  // 16 warp-arrives
        }
    }
    __syncthreads();
    asm volatile("fence.proxy.async.shared::cta;" ::: "memory");

    // Split tiles 50/50: [0, NT_TMA) streamed via TMA ring,
    // [NT_TMA, NT) consumed via LDG prefetch. n=2^24 -> NT=4096, NT_TMA=2048.
    const int NT = n4 / TILE_F4;
    const int NT_TMA = NT / 2;
    const int M_tma = (NT_TMA > bid) ? (NT_TMA - bid + GRID - 1) / GRID : 0;
    const int NT_LDG = NT - NT_TMA;
    const int M_ldg = (NT_LDG > bid) ? (NT_LDG - bid + GRID - 1) / GRID : 0;
    const int M = (M_tma > M_ldg) ? M_tma : M_ldg;

    // Residual elements beyond NT*TILE_F4 (none for n=2^24): blk 0 consumers.
    if (bid == 0 && tid < CTHREADS) {
        for (int idx = NT * TILE_F4 + tid; idx < n4; idx += CTHREADS) {
            float4 p = __ldg(&pred[idx]);
            float4 t = __ldg(&target[idx]);
            process4(my, p, t);
        }
    }

    if (warp == CWARPS) {
        // ── Producer warp: elected lane drives the TMA ring ────────────
        if (lane == 0) {
            for (int k = 0; k < M_tma; k++) {
                int s = k & (STAGES - 1);
                uint32_t pe = (((unsigned)k >> 2) & 1u) ^ 1u;   // start phase 1
                mbar_wait(sbase + SMEM_EMPTY_OFF + s * 8, pe);
                int t = bid + k * GRID;
                uint32_t bar = sbase + SMEM_FULL_OFF + s * 8;
                uint32_t dst = sbase + SMEM_TILES_OFF + s * STAGE_BYTES;
                mbar_expect_tx(bar, STAGE_BYTES);
                bulk_g2s(dst, pred + (size_t)t * TILE_F4, TILE_BYTES, bar);
                bulk_g2s(dst + TILE_BYTES, target + (size_t)t * TILE_F4, TILE_BYTES, bar);
            }
        }
    } else {
        // ── Consumers: LDG prefetch -> TMA tile -> LDG data ────────────
        for (int k = 0; k < M; k++) {
            // 1) Issue LDG prefetch for the mirrored tile FIRST: these 4
            //    LDG.128 ride out DRAM latency during the mbar wait + smem
            //    consume, adding a second independent BW stream.
            int t2 = NT_TMA + bid + k * GRID;
            bool lv = t2 < NT;
            float4 lp0, lt0, lp1, lt1;
            if (lv) {
                const float4* pB = pred + (size_t)t2 * TILE_F4;
                const float4* tB = target + (size_t)t2 * TILE_F4;
                lp0 = __ldg(&pB[tid]);
                lp1 = __ldg(&pB[tid + CTHREADS]);
                lt0 = __ldg(&tB[tid]);
                lt1 = __ldg(&tB[tid + CTHREADS]);
            }

            // 2) TMA tile from the ring.
            if (k < M_tma) {
                int s = k & (STAGES - 1);
                uint32_t pf = ((unsigned)k >> 2) & 1u;
                mbar_wait(sbase + SMEM_FULL_OFF + s * 8, pf);

                const float4* pb = (const float4*)(smem + SMEM_TILES_OFF + s * STAGE_BYTES);
                const float4* tb = pb + TILE_F4;
                float4 p0 = pb[tid],            t0 = tb[tid];
                float4 p1 = pb[tid + CTHREADS], t1 = tb[tid + CTHREADS];
                process4(my, p0, t0);
                process4(my, p1, t1);

                __syncwarp();
                if (lane == 0) mbar_arrive(sbase + SMEM_EMPTY_OFF + s * 8);
            }

            // 3) Consume the prefetched LDG tile.
            if (lv) {
                process4(my, lp0, lt0);
                process4(my, lp1, lt1);
            }
        }
    }
    __syncthreads();

    // ── Block reduction ────────────────────────────────────────────────
    if (tid < NUM_BINS * CWARPS) {
        int b = tid / CWARPS;
        int w = tid % CWARPS;
        const float* cell = hist + w * (NUM_BINS * 32) + b * 32;
        float s = 0.0f, cnt = 0.0f;
        #pragma unroll
        for (int l = 0; l < 32; l++) {
            float acc = cell[l];
            float c = rintf(acc * (1.0f / PACK));   // exact: sum-part < PACK/2
            s += acc - c * PACK;                    // exact subtraction
            cnt += c;
        }
        s_red[b * CWARPS + w] = make_float2(s, cnt);
    }
    __syncthreads();

    if (tid < NUM_BINS) {
        int b = tid;
        float s = 0.0f, cnt = 0.0f;
        #pragma unroll
        for (int w = 0; w < CWARPS; w++) {
            float2 v = s_red[b * CWARPS + w];
            s += v.x; cnt += v.y;
        }
        g_part[b * GRID + bid] = make_float2(s, cnt);
    }

    // ── Last-block finalize ────────────────────────────────────────────
    __syncthreads();
    if (tid == 0) {
        __threadfence();
        unsigned old = atomicAdd(&g_done, 1u);
        s_is_last = (old == GRID - 1);
    }
    __syncthreads();
    if (!s_is_last) return;

    if (warp < CWARPS) {
        for (int b = warp; b < NUM_BINS; b += CWARPS) {
            float s = 0.0f, c = 0.0f;
            for (int i = lane; i < GRID; i += 32) {
                float2 v = __ldcg(&g_part[b * GRID + i]);   // L2-resident
                s += v.x; c += v.y;    // counts integer fp32 < 2^24: exact
            }
            #pragma unroll
            for (int o = 16; o; o >>= 1) {
                s += __shfl_xor_sync(0xFFFFFFFFu, s, o);
                c += __shfl_xor_sync(0xFFFFFFFFu, c, o);
            }
            if (lane == 0) { f_sum[b] = s; f_cnt[b] = c; }
        }
    }
    __syncthreads();

    if (tid < NUM_BINS)
        f_w[tid] = powf(fmaxf(f_cnt[tid], 1.0f), -0.9f);
    __syncthreads();

    if (tid == 0) {
        float tot = 0.0f;
        #pragma unroll
        for (int b = 0; b < NUM_BINS; b++) tot += f_w[b];
        float acc = 0.0f;
        #pragma unroll
        for (int b = 0; b < NUM_BINS; b++) {
            float wb = (tot > 0.0f) ? (f_w[b] / tot * (float)NUM_BINS) : f_w[b];
            wb = fmaxf(wb, 1.0f);
            acc += wb * f_sum[b];
        }
        *out = acc / (float)n;
        g_done = 0;   // reset for next graph replay
    }
}

extern "C" void kernel_launch(void* const* d_in, const int* in_sizes, int n_in,
                              void* d_out, int out_size) {
    const float* pred = (const float*)d_in[0];
    const float* target = (const float*)d_in[1];
    int n = in_sizes[0];
    int n4 = n / 4;   // n = 2^24

    cudaFuncSetAttribute(dwmse_hybrid_kernel,
                         cudaFuncAttributeMaxDynamicSharedMemorySize, SMEM_SIZE);
    dwmse_hybrid_kernel<<<GRID, THREADS, SMEM_SIZE>>>((const float4*)pred,
                                                      (const float4*)target,
                                                      n4, (float*)d_out, n);
}

// round 14
// speedup vs baseline: 1.0195x; 1.0195x over previous
#include <cuda_runtime.h>
#include <cstdint>

#define NUM_BINS 20
#define CWARPS 8           // consumer warps per CTA
#define CTHREADS 256       // consumer threads per CTA
#define THREADS 288        // + 1 producer warp
#define GRID 296           // persistent: 2 CTAs/SM, phase-decoupled
#define STAGES 4
#define TILE_F4 512        // float4 per array per tile (8KB)
#define TILE_BYTES 8192
#define STAGE_BYTES (2 * TILE_BYTES)
#define PACK 512.0f        // packed cell: 512*count + sum_sq_err
                           // <=222 elem/thread, se<1 -> sum-part < 256: exact

#define SMEM_HIST_FLOATS (CWARPS * NUM_BINS * 32)          // 5120 = 20KB
#define SMEM_TILES_OFF   (SMEM_HIST_FLOATS * 4)            // 20480
#define SMEM_FULL_OFF    (SMEM_TILES_OFF + STAGES * STAGE_BYTES)  // 86016
#define SMEM_EMPTY_OFF   (SMEM_FULL_OFF + STAGES * 8)
#define SMEM_SIZE        (SMEM_EMPTY_OFF + STAGES * 8)     // 86080 (*2 = 172KB/SM)

__device__ float2 g_part[NUM_BINS * GRID];
__device__ unsigned g_done;   // zero at module load; reset by last block

// ── PTX helpers ─────────────────────────────────────────────────────────
__device__ __forceinline__ uint32_t smem_u32(const void* p) {
    uint32_t a;
    asm("{ .reg .u64 t; cvta.to.shared.u64 t, %1; cvt.u32.u64 %0, t; }"
        : "=r"(a) : "l"(p));
    return a;
}
__device__ __forceinline__ void mbar_init(uint32_t bar, uint32_t cnt) {
    asm volatile("mbarrier.init.shared.b64 [%0], %1;" :: "r"(bar), "r"(cnt) : "memory");
}
__device__ __forceinline__ void mbar_expect_tx(uint32_t bar, uint32_t bytes) {
    asm volatile("mbarrier.arrive.expect_tx.shared.b64 _, [%0], %1;"
                 :: "r"(bar), "r"(bytes) : "memory");
}
__device__ __forceinline__ void mbar_arrive(uint32_t bar) {
    asm volatile("mbarrier.arrive.shared.b64 _, [%0];" :: "r"(bar) : "memory");
}
__device__ __forceinline__ void mbar_wait(uint32_t bar, uint32_t parity) {
    asm volatile(
        "{\n\t.reg .pred P;\n\t"
        "W%=:\n\t"
        "mbarrier.try_wait.parity.acquire.cta.shared::cta.b64 P, [%0], %1, 0x989680;\n\t"
        "@P bra D%=;\n\t"
        "bra W%=;\n\t"
        "D%=:\n\t}"
        :: "r"(bar), "r"(parity) : "memory");
}
__device__ __forceinline__ void bulk_g2s(uint32_t dst, const void* src,
                                         uint32_t bytes, uint32_t bar) {
    asm volatile(
        "cp.async.bulk.shared::cta.global.mbarrier::complete_tx::bytes "
        "[%0], [%1], %2, [%3];"
        :: "r"(dst), "l"(src), "r"(bytes), "r"(bar) : "memory");
}

// ── packed histogram update for 4 element-pairs ─────────────────────────
__device__ __forceinline__ void process4(float* my, float4 p, float4 t) {
    float d0 = p.x - t.x, d1 = p.y - t.y, d2 = p.z - t.z, d3 = p.w - t.w;
    float v0 = fmaf(d0, d0, PACK), v1 = fmaf(d1, d1, PACK);
    float v2 = fmaf(d2, d2, PACK), v3 = fmaf(d3, d3, PACK);
    // target in [0,1): trunc == floor, only upper clamp needed
    int b0 = min((int)(t.x * 20.0f), NUM_BINS - 1);
    int b1 = min((int)(t.y * 20.0f), NUM_BINS - 1);
    int b2 = min((int)(t.z * 20.0f), NUM_BINS - 1);
    int b3 = min((int)(t.w * 20.0f), NUM_BINS - 1);
    my[b0 * 32] += v0;
    my[b1 * 32] += v1;
    my[b2 * 32] += v2;
    my[b3 * 32] += v3;
}

__global__ __launch_bounds__(THREADS, 2) void dwmse_ws2_kernel(
    const float4* __restrict__ pred,
    const float4* __restrict__ target,
    int n4, float* __restrict__ out, int n)
{
    extern __shared__ char smem[];
    float* hist = (float*)smem;
    const uint32_t sbase = smem_u32(smem);

    __shared__ float2 s_red[NUM_BINS * CWARPS];
    __shared__ bool s_is_last;
    __shared__ float f_sum[NUM_BINS], f_cnt[NUM_BINS], f_w[NUM_BINS];

    const int tid = threadIdx.x;
    const int lane = tid & 31;
    const int warp = tid >> 5;
    const int bid = blockIdx.x;
    float* my = hist + warp * (NUM_BINS * 32) + lane;   // valid for warp < 8

    for (int i = tid; i < SMEM_HIST_FLOATS; i += THREADS) hist[i] = 0.0f;

    if (tid == 0) {
        for (int s = 0; s < STAGES; s++) {
            mbar_init(sbase + SMEM_FULL_OFF + s * 8, 1);        // tx-based
            mbar_init(sbase + SMEM_EMPTY_OFF + s * 8, CWARPS);  // 8 warp-arrives
        }
    }
    __syncthreads();
    asm volatile("fence.proxy.async.shared::cta;" ::: "memory");

    // Tiles: t = bid + k*GRID. n=2^24 -> NT=8192; 8192 = 27.7*296 (ragged,
    // handled by per-block M). No sub-tile residual (n4 % TILE_F4 == 0).
    const int NT = n4 / TILE_F4;
    const int M = (NT > bid) ? (NT - bid + GRID - 1) / GRID : 0;

    // General-case residual guard (none for n=2^24).
    if (bid == 0 && tid < CTHREADS) {
        for (int idx = NT * TILE_F4 + tid; idx < n4; idx += CTHREADS) {
            float4 p = __ldg(&pred[idx]);
            float4 t = __ldg(&target[idx]);
            process4(my, p, t);
        }
    }

    if (warp == CWARPS) {
        // ── Producer warp: elected lane drives the ring ────────────────
        if (lane == 0) {
            for (int k = 0; k < M; k++) {
                int s = k & (STAGES - 1);
                uint32_t pe = (((unsigned)k >> 2) & 1u) ^ 1u;   // start phase 1
                mbar_wait(sbase + SMEM_EMPTY_OFF + s * 8, pe);
                int t = bid + k * GRID;
                uint32_t bar = sbase + SMEM_FULL_OFF + s * 8;
                uint32_t dst = sbase + SMEM_TILES_OFF + s * STAGE_BYTES;
                mbar_expect_tx(bar, STAGE_BYTES);
                bulk_g2s(dst, pred + (size_t)t * TILE_F4, TILE_BYTES, bar);
                bulk_g2s(dst + TILE_BYTES, target + (size_t)t * TILE_F4, TILE_BYTES, bar);
            }
        }
    } else {
        // ── Consumer warps: wait full -> consume slice -> arrive empty ──
        for (int k = 0; k < M; k++) {
            int s = k & (STAGES - 1);
            uint32_t pf = ((unsigned)k >> 2) & 1u;
            mbar_wait(sbase + SMEM_FULL_OFF + s * 8, pf);

            const float4* pb = (const float4*)(smem + SMEM_TILES_OFF + s * STAGE_BYTES);
            const float4* tb = pb + TILE_F4;
            float4 p0 = pb[tid],            t0 = tb[tid];
            float4 p1 = pb[tid + CTHREADS], t1 = tb[tid + CTHREADS];
            process4(my, p0, t0);
            process4(my, p1, t1);

            __syncwarp();
            if (lane == 0) mbar_arrive(sbase + SMEM_EMPTY_OFF + s * 8);
        }
    }
    __syncthreads();

    // ── Block reduction ────────────────────────────────────────────────
    // Stage 1: 160 threads; each decodes one (bin,warp) column of 32 cells.
    if (tid < NUM_BINS * CWARPS) {
        int b = tid / CWARPS;
        int w = tid % CWARPS;
        const float* cell = hist + w * (NUM_BINS * 32) + b * 32;
        float s = 0.0f, cnt = 0.0f;
        #pragma unroll
        for (int l = 0; l < 32; l++) {
            float acc = cell[l];
            float c = rintf(acc * (1.0f / PACK));   // exact: sum-part < PACK/2
            s += acc - c * PACK;                    // exact subtraction
            cnt += c;
        }
        s_red[b * CWARPS + w] = make_float2(s, cnt);
    }
    __syncthreads();

    if (tid < NUM_BINS) {
        int b = tid;
        float s = 0.0f, cnt = 0.0f;
        #pragma unroll
        for (int w = 0; w < CWARPS; w++) {
            float2 v = s_red[b * CWARPS + w];
            s += v.x; cnt += v.y;
        }
        g_part[b * GRID + bid] = make_float2(s, cnt);
    }

    // ── Last-block finalize ────────────────────────────────────────────
    __syncthreads();
    if (tid == 0) {
        __threadfence();
        unsigned old = atomicAdd(&g_done, 1u);
        s_is_last = (old == GRID - 1);
    }
    __syncthreads();
    if (!s_is_last) return;

    if (warp < CWARPS) {
        for (int b = warp; b < NUM_BINS; b += CWARPS) {
            float s = 0.0f, c = 0.0f;
            for (int i = lane; i < GRID; i += 32) {
                float2 v = __ldcg(&g_part[b * GRID + i]);   // L2-resident
                s += v.x; c += v.y;    // counts integer fp32 < 2^24: exact
            }
            #pragma unroll
            for (int o = 16; o; o >>= 1) {
                s += __shfl_xor_sync(0xFFFFFFFFu, s, o);
                c += __shfl_xor_sync(0xFFFFFFFFu, c, o);
            }
            if (lane == 0) { f_sum[b] = s; f_cnt[b] = c; }
        }
    }
    __syncthreads();

    if (tid < NUM_BINS)
        f_w[tid] = powf(fmaxf(f_cnt[tid], 1.0f), -0.9f);
    __syncthreads();

    if (tid == 0) {
        float tot = 0.0f;
        #pragma unroll
        for (int b = 0; b < NUM_BINS; b++) tot += f_w[b];
        float acc = 0.0f;
        #pragma unroll
        for (int b = 0; b < NUM_BINS; b++) {
            float wb = (tot > 0.0f) ? (f_w[b] / tot * (float)NUM_BINS) : f_w[b];
            wb = fmaxf(wb, 1.0f);
            acc += wb * f_sum[b];
        }
        *out = acc / (float)n;
        g_done = 0;   // reset for next graph replay
    }
}

extern "C" void kernel_launch(void* const* d_in, const int* in_sizes, int n_in,
                              void* d_out, int out_size) {
    const float* pred = (const float*)d_in[0];
    const float* target = (const float*)d_in[1];
    int n = in_sizes[0];
    int n4 = n / 4;   // n = 2^24

    cudaFuncSetAttribute(dwmse_ws2_kernel,
                         cudaFuncAttributeMaxDynamicSharedMemorySize, SMEM_SIZE);
    dwmse_ws2_kernel<<<GRID, THREADS, SMEM_SIZE>>>((const float4*)pred,
                                                   (const float4*)target,
                                                   n4, (float*)d_out, n);
}